// round 2
// baseline (speedup 1.0000x reference)
#include <cuda_runtime.h>
#include <cuda_bf16.h>
#include <cstdint>

#define OPT 64
#define DIN 128
#define DOUT 128
#define TILE_M 64
#define NTHREADS 256
#define MAX_B 16384

// Scratch (no device allocation allowed)
__device__ int g_counts[OPT];
__device__ int g_offsets[OPT + 1];
__device__ int g_cursor[OPT];
__device__ int g_rowids[MAX_B];

__global__ void zero_kernel() {
    int t = threadIdx.x;
    if (t < OPT) { g_counts[t] = 0; g_cursor[t] = 0; }
}

__global__ void count_kernel(const int* __restrict__ idx, int B) {
    int i = blockIdx.x * blockDim.x + threadIdx.x;
    if (i < B) {
        int e = idx[i];
        if (e >= 0 && e < OPT) atomicAdd(&g_counts[e], 1);
    }
}

__global__ void scan_kernel() {
    if (threadIdx.x == 0) {
        int s = 0;
        for (int e = 0; e < OPT; e++) { g_offsets[e] = s; s += g_counts[e]; }
        g_offsets[OPT] = s;
    }
}

__global__ void scatter_kernel(const int* __restrict__ idx, int B) {
    int i = blockIdx.x * blockDim.x + threadIdx.x;
    if (i < B) {
        int e = idx[i];
        if (e >= 0 && e < OPT) {
            int p = g_offsets[e] + atomicAdd(&g_cursor[e], 1);
            g_rowids[p] = i;
        }
    }
}

// Compute: blockIdx.x = expert, blockIdx.y = row tile within that expert.
// SMEM layout: w[e] [128][128] fp32 (64KB) | x tile [64][128] fp32 (32KB) | rowids [64]
#define SMEM_BYTES (DIN * DOUT * 4 + TILE_M * DIN * 4 + TILE_M * 4)

__global__ __launch_bounds__(NTHREADS, 2)
void mm_kernel(const float* __restrict__ x, const float* __restrict__ w,
               const float* __restrict__ bias, float* __restrict__ out) {
    int e = blockIdx.x;
    int start = g_offsets[e];
    int end = g_offsets[e + 1];
    int m0 = start + blockIdx.y * TILE_M;
    if (m0 >= end) return;
    int mcnt = min(TILE_M, end - m0);

    extern __shared__ float smem[];
    float* sw = smem;                         // [DIN][DOUT] (k-major, same as global)
    float* sx = smem + DIN * DOUT;            // [TILE_M][DIN]
    int* srow = (int*)(sx + TILE_M * DIN);    // [TILE_M]

    int t = threadIdx.x;

    // Load w[e] (16384 floats) via float4, fully coalesced
    {
        const float4* wg = (const float4*)(w + (size_t)e * DIN * DOUT);
        float4* swv = (float4*)sw;
        #pragma unroll
        for (int i = t; i < DIN * DOUT / 4; i += NTHREADS) swv[i] = wg[i];
    }

    // Load gathered input rows + stash row ids
    for (int r = t; r < TILE_M; r += NTHREADS)
        srow[r] = (r < mcnt) ? g_rowids[m0 + r] : -1;
    for (int i = t; i < mcnt * (DIN / 4); i += NTHREADS) {
        int r = i / (DIN / 4);
        int c = i % (DIN / 4);
        int gr = g_rowids[m0 + r];
        ((float4*)(sx + r * DIN))[c] = ((const float4*)(x + (size_t)gr * DIN))[c];
    }
    __syncthreads();

    // Each thread: 8 rows x 4 cols of output
    int lane = t & 31;       // col group: cols [4*lane, 4*lane+4)
    int rg = t >> 5;         // row group: rows [8*rg, 8*rg+8)

    float acc[8][4];
    #pragma unroll
    for (int r = 0; r < 8; r++)
        #pragma unroll
        for (int j = 0; j < 4; j++) acc[r][j] = 0.0f;

    const float* sxb = sx + (rg * 8) * DIN;

    #pragma unroll 4
    for (int k = 0; k < DIN; k++) {
        float4 wv = *(const float4*)(sw + k * DOUT + 4 * lane);
        #pragma unroll
        for (int r = 0; r < 8; r++) {
            float xv = sxb[r * DIN + k];   // warp-broadcast (all lanes same addr)
            acc[r][0] = fmaf(xv, wv.x, acc[r][0]);
            acc[r][1] = fmaf(xv, wv.y, acc[r][1]);
            acc[r][2] = fmaf(xv, wv.z, acc[r][2]);
            acc[r][3] = fmaf(xv, wv.w, acc[r][3]);
        }
    }

    // Bias + writeback
    float4 bv = ((const float4*)(bias + (size_t)e * DOUT))[lane];
    #pragma unroll
    for (int r = 0; r < 8; r++) {
        int row = rg * 8 + r;
        if (row < mcnt) {
            int gr = srow[row];
            float4 o;
            o.x = acc[r][0] + bv.x;
            o.y = acc[r][1] + bv.y;
            o.z = acc[r][2] + bv.z;
            o.w = acc[r][3] + bv.w;
            *(float4*)(out + (size_t)gr * DOUT + 4 * lane) = o;
        }
    }
}

extern "C" void kernel_launch(void* const* d_in, const int* in_sizes, int n_in,
                              void* d_out, int out_size) {
    const float* x = (const float*)d_in[0];
    const float* w = (const float*)d_in[1];
    const float* b = (const float*)d_in[2];
    const int* idx = (const int*)d_in[3];   // JAX default: int64 silently -> int32
    float* out = (float*)d_out;
    int B = in_sizes[3];   // indices element count

    cudaFuncSetAttribute(mm_kernel, cudaFuncAttributeMaxDynamicSharedMemorySize,
                         SMEM_BYTES);

    zero_kernel<<<1, 64>>>();
    count_kernel<<<(B + 255) / 256, 256>>>(idx, B);
    scan_kernel<<<1, 32>>>();
    scatter_kernel<<<(B + 255) / 256, 256>>>(idx, B);

    // grid.y = 64 tiles covers up to 4096 rows per expert (mean is 256)
    dim3 grid(OPT, 64);
    mm_kernel<<<grid, NTHREADS, SMEM_BYTES>>>(x, w, b, out);
}

// round 3
// speedup vs baseline: 1.2257x; 1.2257x over previous
#include <cuda_runtime.h>
#include <cstdint>

#define OPT 64
#define DIN 128
#define DOUT 128
#define TILE_M 64
#define MAX_B 16384
#define HBLK 64                               // max histogram blocks (B/256)
#define MAX_TILES (MAX_B / TILE_M + OPT)      // 320

// Scratch (device allocation is banned)
__device__ int g_blockhist[HBLK][OPT];
__device__ int g_blockbase[HBLK][OPT];
__device__ int g_expert_end[OPT];
__device__ int g_rowids[MAX_B];
__device__ int g_ntiles;
__device__ int g_tile_e[MAX_TILES];
__device__ int g_tile_m0[MAX_TILES];

// ---------------- Prelude: counting sort by expert, no global atomics ----------------

__global__ void hist_kernel(const int* __restrict__ idx, int B) {
    __shared__ int h[OPT];
    int t = threadIdx.x;
    if (t < OPT) h[t] = 0;
    __syncthreads();
    int i = blockIdx.x * 256 + t;
    if (i < B) {
        int e = idx[i];
        if (e >= 0 && e < OPT) atomicAdd(&h[e], 1);
    }
    __syncthreads();
    if (t < OPT) g_blockhist[blockIdx.x][t] = h[t];
}

__global__ void scan_kernel(int B) {
    __shared__ int tot[OPT];
    __shared__ int off[OPT];
    __shared__ int toff[OPT];
    int e = threadIdx.x;  // 64 threads
    int nblk = (B + 255) / 256;
    int s = 0;
    for (int b = 0; b < nblk; b++) s += g_blockhist[b][e];
    tot[e] = s;
    __syncthreads();
    if (e == 0) {
        int acc = 0, tacc = 0;
        for (int i = 0; i < OPT; i++) {
            off[i] = acc; acc += tot[i];
            toff[i] = tacc; tacc += (tot[i] + TILE_M - 1) / TILE_M;
        }
        g_ntiles = tacc;
    }
    __syncthreads();
    int run = off[e];
    for (int b = 0; b < nblk; b++) { g_blockbase[b][e] = run; run += g_blockhist[b][e]; }
    g_expert_end[e] = off[e] + tot[e];
    int nt = (tot[e] + TILE_M - 1) / TILE_M;
    for (int i = 0; i < nt; i++) {
        g_tile_e[toff[e] + i] = e;
        g_tile_m0[toff[e] + i] = off[e] + i * TILE_M;
    }
}

__global__ void scatter_kernel(const int* __restrict__ idx, int B) {
    __shared__ int cur[OPT];
    int t = threadIdx.x;
    if (t < OPT) cur[t] = 0;
    __syncthreads();
    int i = blockIdx.x * 256 + t;
    if (i < B) {
        int e = idx[i];
        if (e >= 0 && e < OPT) {
            int r = atomicAdd(&cur[e], 1);          // smem atomic only
            g_rowids[g_blockbase[blockIdx.x][e] + r] = i;
        }
    }
}

// ---------------- Compute: one block per (expert, 64-row) tile ----------------
// 128 threads; each owns 8 rows x 8 cols via packed f32x2 FFMA.

#define NT 128
#define SMEM_BYTES (DIN * DOUT * 4 + TILE_M * DIN * 4 + TILE_M * 4)

__device__ __forceinline__ unsigned long long ffma2(unsigned long long a,
                                                    unsigned long long b,
                                                    unsigned long long c) {
    unsigned long long d;
    asm("fma.rn.f32x2 %0, %1, %2, %3;" : "=l"(d) : "l"(a), "l"(b), "l"(c));
    return d;
}

__device__ __forceinline__ unsigned long long dup2(float v) {
    unsigned long long d;
    asm("mov.b64 %0, {%1, %1};" : "=l"(d) : "f"(v));
    return d;
}

__global__ __launch_bounds__(NT, 2)
void mm_kernel(const float* __restrict__ x, const float* __restrict__ w,
               const float* __restrict__ bias, float* __restrict__ out) {
    int tile = blockIdx.x;
    if (tile >= g_ntiles) return;
    int e = g_tile_e[tile];
    int m0 = g_tile_m0[tile];
    int mcnt = min(TILE_M, g_expert_end[e] - m0);

    extern __shared__ float smem[];
    float* sw = smem;                       // [DIN][DOUT] k-major, 64 KB
    float* sx = smem + DIN * DOUT;          // [TILE_M][DIN], 32 KB
    int* srow = (int*)(sx + TILE_M * DIN);  // [TILE_M]

    int t = threadIdx.x;

    // Stage w[e] (coalesced float4)
    {
        const float4* wg = (const float4*)(w + (size_t)e * DIN * DOUT);
        float4* swv = (float4*)sw;
        #pragma unroll
        for (int i = t; i < DIN * DOUT / 4; i += NT) swv[i] = wg[i];
    }
    // Stage gathered x rows + row ids
    for (int r = t; r < TILE_M; r += NT)
        srow[r] = (r < mcnt) ? g_rowids[m0 + r] : 0;
    for (int i = t; i < mcnt * (DIN / 4); i += NT) {
        int r = i >> 5;          // DIN/4 = 32 float4 per row
        int c = i & 31;
        int gr = g_rowids[m0 + r];
        ((float4*)(sx + r * DIN))[c] = ((const float4*)(x + (size_t)gr * DIN))[c];
    }
    __syncthreads();

    int cg = t & 15;    // cols [8*cg, 8*cg+8)
    int rg = t >> 4;    // rows [8*rg, 8*rg+8)

    // Accumulators start at bias (bit-cast pairs of floats as packed f32x2)
    unsigned long long acc[8][4];
    {
        const ulonglong2* bv = (const ulonglong2*)(bias + (size_t)e * DOUT + 8 * cg);
        ulonglong2 b01 = bv[0];
        ulonglong2 b23 = bv[1];
        #pragma unroll
        for (int r = 0; r < 8; r++) {
            acc[r][0] = b01.x; acc[r][1] = b01.y;
            acc[r][2] = b23.x; acc[r][3] = b23.y;
        }
    }

    const float* sxb = sx + rg * 8 * DIN;
    const char* swb = (const char*)sw + 32 * cg;   // byte offset of this thread's 8 cols

    #pragma unroll 2
    for (int k = 0; k < DIN; k++) {
        ulonglong2 w01 = *(const ulonglong2*)(swb + (size_t)k * DOUT * 4);
        ulonglong2 w23 = *(const ulonglong2*)(swb + (size_t)k * DOUT * 4 + 16);
        #pragma unroll
        for (int r = 0; r < 8; r++) {
            unsigned long long xx = dup2(sxb[r * DIN + k]);  // broadcast LDS
            acc[r][0] = ffma2(xx, w01.x, acc[r][0]);
            acc[r][1] = ffma2(xx, w01.y, acc[r][1]);
            acc[r][2] = ffma2(xx, w23.x, acc[r][2]);
            acc[r][3] = ffma2(xx, w23.y, acc[r][3]);
        }
    }

    // Writeback (two STG.128 per live row)
    #pragma unroll
    for (int r = 0; r < 8; r++) {
        int row = rg * 8 + r;
        if (row < mcnt) {
            int gr = srow[row];
            ulonglong2* o = (ulonglong2*)(out + (size_t)gr * DOUT + 8 * cg);
            o[0] = make_ulonglong2(acc[r][0], acc[r][1]);
            o[1] = make_ulonglong2(acc[r][2], acc[r][3]);
        }
    }
}

extern "C" void kernel_launch(void* const* d_in, const int* in_sizes, int n_in,
                              void* d_out, int out_size) {
    const float* x = (const float*)d_in[0];
    const float* w = (const float*)d_in[1];
    const float* b = (const float*)d_in[2];
    const int* idx = (const int*)d_in[3];   // JAX default x64-disabled: int32
    float* out = (float*)d_out;
    int B = in_sizes[3];
    if (B > MAX_B) B = MAX_B;

    cudaFuncSetAttribute(mm_kernel, cudaFuncAttributeMaxDynamicSharedMemorySize,
                         SMEM_BYTES);

    int nblk = (B + 255) / 256;   // <= HBLK for B <= 16384
    hist_kernel<<<nblk, 256>>>(idx, B);
    scan_kernel<<<1, 64>>>(B);
    scatter_kernel<<<nblk, 256>>>(idx, B);
    mm_kernel<<<MAX_TILES, NT, SMEM_BYTES>>>(x, w, b, out);
}